// round 1
// baseline (speedup 1.0000x reference)
#include <cuda_runtime.h>
#include <cuda_bf16.h>

// -(1/B) * sum(preds_t * log(preds_s)),  B = 4096, C = 1000 (shapes fixed by problem)

#define NBLK 1024
#define NTHR 256

__device__ float g_partials[NBLK];

__global__ __launch_bounds__(NTHR) void reduce_pass1(
    const float* __restrict__ s, const float* __restrict__ t, int n_vec, int n_tail_start, int n)
{
    float acc = 0.0f;
    const float4* s4 = reinterpret_cast<const float4*>(s);
    const float4* t4 = reinterpret_cast<const float4*>(t);

    int idx = blockIdx.x * NTHR + threadIdx.x;
    int stride = NBLK * NTHR;
    for (int i = idx; i < n_vec; i += stride) {
        float4 sv = s4[i];
        float4 tv = t4[i];
        acc += tv.x * __logf(sv.x);
        acc += tv.y * __logf(sv.y);
        acc += tv.z * __logf(sv.z);
        acc += tv.w * __logf(sv.w);
    }
    // tail (n not divisible by 4) — handled by block 0 threads
    if (blockIdx.x == 0) {
        for (int i = n_tail_start + threadIdx.x; i < n; i += NTHR)
            acc += t[i] * __logf(s[i]);
    }

    // warp reduce
    #pragma unroll
    for (int off = 16; off > 0; off >>= 1)
        acc += __shfl_xor_sync(0xFFFFFFFFu, acc, off);

    __shared__ float warp_sums[NTHR / 32];
    int lane = threadIdx.x & 31;
    int wid = threadIdx.x >> 5;
    if (lane == 0) warp_sums[wid] = acc;
    __syncthreads();

    if (wid == 0) {
        float v = (lane < NTHR / 32) ? warp_sums[lane] : 0.0f;
        #pragma unroll
        for (int off = 4; off > 0; off >>= 1)
            v += __shfl_xor_sync(0xFFFFFFFFu, v, off);
        if (lane == 0) g_partials[blockIdx.x] = v;
    }
}

__global__ __launch_bounds__(NTHR) void reduce_pass2(float* __restrict__ out, float inv_B)
{
    float acc = 0.0f;
    for (int i = threadIdx.x; i < NBLK; i += NTHR)
        acc += g_partials[i];

    #pragma unroll
    for (int off = 16; off > 0; off >>= 1)
        acc += __shfl_xor_sync(0xFFFFFFFFu, acc, off);

    __shared__ float warp_sums[NTHR / 32];
    int lane = threadIdx.x & 31;
    int wid = threadIdx.x >> 5;
    if (lane == 0) warp_sums[wid] = acc;
    __syncthreads();

    if (wid == 0) {
        float v = (lane < NTHR / 32) ? warp_sums[lane] : 0.0f;
        #pragma unroll
        for (int off = 4; off > 0; off >>= 1)
            v += __shfl_xor_sync(0xFFFFFFFFu, v, off);
        if (lane == 0) out[0] = -v * inv_B;
    }
}

extern "C" void kernel_launch(void* const* d_in, const int* in_sizes, int n_in,
                              void* d_out, int out_size)
{
    const float* s = (const float*)d_in[0];  // preds_s
    const float* t = (const float*)d_in[1];  // preds_t
    float* out = (float*)d_out;

    int n = in_sizes[0];
    int n_vec = n / 4;
    int n_tail_start = n_vec * 4;

    const float inv_B = 1.0f / 4096.0f;  // B fixed by problem shape

    reduce_pass1<<<NBLK, NTHR>>>(s, t, n_vec, n_tail_start, n);
    reduce_pass2<<<1, NTHR>>>(out, inv_B);
}

// round 3
// speedup vs baseline: 1.0344x; 1.0344x over previous
#include <cuda_runtime.h>
#include <cuda_bf16.h>

// -(1/B) * sum(preds_t * log(preds_s)),  B = 4096, C = 1000  (n = 4,096,000)
// Single-kernel reduction: grid partials + last-block-done final fold.

#define NBLK 1024
#define NTHR 256

__device__ float g_partials[NBLK];
__device__ unsigned int g_ticket;   // zero-initialized; reset by last block each call

__device__ __forceinline__ float block_reduce(float acc, float* warp_sums)
{
    #pragma unroll
    for (int off = 16; off > 0; off >>= 1)
        acc += __shfl_xor_sync(0xFFFFFFFFu, acc, off);

    int lane = threadIdx.x & 31;
    int wid  = threadIdx.x >> 5;
    if (lane == 0) warp_sums[wid] = acc;
    __syncthreads();

    float v = 0.0f;
    if (wid == 0) {
        v = (lane < NTHR / 32) ? warp_sums[lane] : 0.0f;
        #pragma unroll
        for (int off = 4; off > 0; off >>= 1)
            v += __shfl_xor_sync(0xFFFFFFFFu, v, off);
    }
    return v;   // valid in warp 0 lane 0
}

__global__ __launch_bounds__(NTHR) void fused_reduce(
    const float* __restrict__ s, const float* __restrict__ t,
    int n_vec, int n_tail_start, int n, float inv_B, float* __restrict__ out)
{
    float acc = 0.0f;
    const float4* s4 = reinterpret_cast<const float4*>(s);
    const float4* t4 = reinterpret_cast<const float4*>(t);

    int idx = blockIdx.x * NTHR + threadIdx.x;
    int stride = NBLK * NTHR;
    for (int i = idx; i < n_vec; i += stride) {
        float4 sv = s4[i];
        float4 tv = t4[i];
        acc += tv.x * __logf(sv.x);
        acc += tv.y * __logf(sv.y);
        acc += tv.z * __logf(sv.z);
        acc += tv.w * __logf(sv.w);
    }
    if (blockIdx.x == 0) {                 // tail (n % 4), empty for this shape
        for (int i = n_tail_start + threadIdx.x; i < n; i += NTHR)
            acc += t[i] * __logf(s[i]);
    }

    __shared__ float warp_sums[NTHR / 32];
    float bsum = block_reduce(acc, warp_sums);

    __shared__ bool is_last;
    if (threadIdx.x == 0) {
        g_partials[blockIdx.x] = bsum;
        __threadfence();
        unsigned int ticket = atomicAdd(&g_ticket, 1u);
        is_last = (ticket == NBLK - 1);
    }
    __syncthreads();

    if (is_last) {
        // final fold: 1024 partials, 4 per thread, L2-resident
        float a = 0.0f;
        #pragma unroll
        for (int k = 0; k < NBLK / NTHR; k++)
            a += g_partials[threadIdx.x + k * NTHR];
        __syncthreads();                    // reuse warp_sums safely
        float total = block_reduce(a, warp_sums);
        if (threadIdx.x == 0) {
            out[0] = -total * inv_B;
            g_ticket = 0;                   // reset for next graph replay
        }
    }
}

extern "C" void kernel_launch(void* const* d_in, const int* in_sizes, int n_in,
                              void* d_out, int out_size)
{
    const float* s = (const float*)d_in[0];  // preds_s
    const float* t = (const float*)d_in[1];  // preds_t
    float* out = (float*)d_out;

    int n = in_sizes[0];
    int n_vec = n / 4;
    int n_tail_start = n_vec * 4;

    const float inv_B = 1.0f / 4096.0f;

    fused_reduce<<<NBLK, NTHR>>>(s, t, n_vec, n_tail_start, n, inv_B, out);
}

// round 4
// speedup vs baseline: 1.0789x; 1.0430x over previous
#include <cuda_runtime.h>
#include <cuda_bf16.h>

// -(1/B) * sum(preds_t * log(preds_s)),  B = 4096, C = 1000  (n = 4,096,000)
// n_vec = 1,024,000 float4 = 500 blocks x 256 threads x 8 vec/thread EXACTLY.

#define NTHR 256
#define VPT  8            // float4 vectors per thread
#define MAXBLK 1024

__device__ float g_partials[MAXBLK];
__device__ unsigned int g_ticket;   // zero-init; reset by last block each call

__device__ __forceinline__ float block_reduce(float acc, float* warp_sums)
{
    #pragma unroll
    for (int off = 16; off > 0; off >>= 1)
        acc += __shfl_xor_sync(0xFFFFFFFFu, acc, off);

    int lane = threadIdx.x & 31;
    int wid  = threadIdx.x >> 5;
    if (lane == 0) warp_sums[wid] = acc;
    __syncthreads();

    float v = 0.0f;
    if (wid == 0) {
        v = (lane < NTHR / 32) ? warp_sums[lane] : 0.0f;
        #pragma unroll
        for (int off = 4; off > 0; off >>= 1)
            v += __shfl_xor_sync(0xFFFFFFFFu, v, off);
    }
    return v;   // valid in warp 0 lane 0
}

__device__ __forceinline__ void finish(float acc, float inv_B, float* out, int nblk)
{
    __shared__ float warp_sums[NTHR / 32];
    float bsum = block_reduce(acc, warp_sums);

    __shared__ bool is_last;
    if (threadIdx.x == 0) {
        g_partials[blockIdx.x] = bsum;
        __threadfence();
        unsigned int ticket = atomicAdd(&g_ticket, 1u);
        is_last = (ticket == (unsigned int)(nblk - 1));
    }
    __syncthreads();

    if (is_last) {
        float a = 0.0f;
        for (int i = threadIdx.x; i < nblk; i += NTHR)
            a += g_partials[i];
        __syncthreads();
        float total = block_reduce(a, warp_sums);
        if (threadIdx.x == 0) {
            out[0] = -total * inv_B;
            g_ticket = 0;                   // reset for next graph replay
        }
    }
}

// Exact-cover kernel: each thread handles VPT strided float4 pairs, no guards.
// Loads front-batched in two groups of 8 LDG.128 to maximize MLP.
__global__ __launch_bounds__(NTHR, 4) void fused_reduce_exact(
    const float4* __restrict__ s4, const float4* __restrict__ t4,
    int stride, float inv_B, float* __restrict__ out, int nblk)
{
    int idx = blockIdx.x * NTHR + threadIdx.x;
    float acc = 0.0f;

    #pragma unroll
    for (int h = 0; h < VPT / 4; h++) {
        float4 sv[4], tv[4];
        #pragma unroll
        for (int u = 0; u < 4; u++) {
            int i = idx + (h * 4 + u) * stride;
            sv[u] = s4[i];
            tv[u] = t4[i];
        }
        #pragma unroll
        for (int u = 0; u < 4; u++) {
            acc += tv[u].x * __logf(sv[u].x);
            acc += tv[u].y * __logf(sv[u].y);
            acc += tv[u].z * __logf(sv[u].z);
            acc += tv[u].w * __logf(sv[u].w);
        }
    }

    finish(acc, inv_B, out, nblk);
}

// Generic fallback (any n), grid-stride. Only used if shape isn't exact-cover.
__global__ __launch_bounds__(NTHR) void fused_reduce_generic(
    const float* __restrict__ s, const float* __restrict__ t,
    int n, float inv_B, float* __restrict__ out, int nblk)
{
    int n_vec = n / 4;
    int tail0 = n_vec * 4;
    const float4* s4 = reinterpret_cast<const float4*>(s);
    const float4* t4 = reinterpret_cast<const float4*>(t);

    float acc = 0.0f;
    int stride = nblk * NTHR;
    for (int i = blockIdx.x * NTHR + threadIdx.x; i < n_vec; i += stride) {
        float4 sv = s4[i];
        float4 tv = t4[i];
        acc += tv.x * __logf(sv.x);
        acc += tv.y * __logf(sv.y);
        acc += tv.z * __logf(sv.z);
        acc += tv.w * __logf(sv.w);
    }
    if (blockIdx.x == 0) {
        for (int i = tail0 + threadIdx.x; i < n; i += NTHR)
            acc += t[i] * __logf(s[i]);
    }

    finish(acc, inv_B, out, nblk);
}

extern "C" void kernel_launch(void* const* d_in, const int* in_sizes, int n_in,
                              void* d_out, int out_size)
{
    const float* s = (const float*)d_in[0];  // preds_s
    const float* t = (const float*)d_in[1];  // preds_t
    float* out = (float*)d_out;

    int n = in_sizes[0];
    float inv_B = (n == 4096000) ? (1.0f / 4096.0f) : (1000.0f / (float)n);

    int n_vec = n / 4;
    int per_block = NTHR * VPT;     // 2048 vectors per block

    if ((n % 4 == 0) && (n_vec % per_block == 0) && (n_vec / per_block) <= MAXBLK) {
        int nblk = n_vec / per_block;           // 500 for this problem
        int stride = nblk * NTHR;               // 128,000
        fused_reduce_exact<<<nblk, NTHR>>>(
            reinterpret_cast<const float4*>(s),
            reinterpret_cast<const float4*>(t),
            stride, inv_B, out, nblk);
    } else {
        int nblk = 1024;
        fused_reduce_generic<<<nblk, NTHR>>>(s, t, n, inv_B, out, nblk);
    }
}

// round 5
// speedup vs baseline: 1.1107x; 1.0295x over previous
#include <cuda_runtime.h>
#include <cuda_bf16.h>

// -(1/B) * sum(preds_t * log(preds_s)),  B = 4096, C = 1000  (n = 4,096,000)
// n_vec = 1,024,000 float4 = 1000 blocks x 256 threads x 4 vec/thread EXACTLY.

#define NTHR 256
#define VPT  4            // float4 vectors per thread (8 LDG.128 incl. both arrays)
#define MAXBLK 2048

__device__ float g_partials[MAXBLK];
__device__ unsigned int g_ticket;   // zero-init; reset by last block each call

__device__ __forceinline__ float block_reduce(float acc, float* warp_sums)
{
    #pragma unroll
    for (int off = 16; off > 0; off >>= 1)
        acc += __shfl_xor_sync(0xFFFFFFFFu, acc, off);

    int lane = threadIdx.x & 31;
    int wid  = threadIdx.x >> 5;
    if (lane == 0) warp_sums[wid] = acc;
    __syncthreads();

    float v = 0.0f;
    if (wid == 0) {
        v = (lane < NTHR / 32) ? warp_sums[lane] : 0.0f;
        #pragma unroll
        for (int off = 4; off > 0; off >>= 1)
            v += __shfl_xor_sync(0xFFFFFFFFu, v, off);
    }
    return v;   // valid in warp 0 lane 0
}

__device__ __forceinline__ void finish(float acc, float inv_B, float* out, int nblk)
{
    __shared__ float warp_sums[NTHR / 32];
    float bsum = block_reduce(acc, warp_sums);

    __shared__ bool is_last;
    if (threadIdx.x == 0) {
        g_partials[blockIdx.x] = bsum;
        __threadfence();
        unsigned int ticket = atomicAdd(&g_ticket, 1u);
        is_last = (ticket == (unsigned int)(nblk - 1));
    }
    __syncthreads();

    if (is_last) {
        float a = 0.0f;
        for (int i = threadIdx.x; i < nblk; i += NTHR)
            a += g_partials[i];
        __syncthreads();
        float total = block_reduce(a, warp_sums);
        if (threadIdx.x == 0) {
            out[0] = -total * inv_B;
            g_ticket = 0;                   // reset for next graph replay
        }
    }
}

// Exact-cover kernel: 4 strided float4 pairs per thread, all 8 LDG.128
// front-batched (MLP_p1 = 8) with no register cap so nothing serializes.
__global__ void fused_reduce_exact(
    const float4* __restrict__ s4, const float4* __restrict__ t4,
    int stride, float inv_B, float* __restrict__ out, int nblk)
{
    int idx = blockIdx.x * NTHR + threadIdx.x;

    float4 sv[VPT], tv[VPT];
    #pragma unroll
    for (int u = 0; u < VPT; u++) {
        int i = idx + u * stride;
        sv[u] = s4[i];
        tv[u] = t4[i];
    }

    float acc = 0.0f;
    #pragma unroll
    for (int u = 0; u < VPT; u++) {
        acc += tv[u].x * __logf(sv[u].x);
        acc += tv[u].y * __logf(sv[u].y);
        acc += tv[u].z * __logf(sv[u].z);
        acc += tv[u].w * __logf(sv[u].w);
    }

    finish(acc, inv_B, out, nblk);
}

// Generic fallback (any n), grid-stride. Only used if shape isn't exact-cover.
__global__ __launch_bounds__(NTHR) void fused_reduce_generic(
    const float* __restrict__ s, const float* __restrict__ t,
    int n, float inv_B, float* __restrict__ out, int nblk)
{
    int n_vec = n / 4;
    int tail0 = n_vec * 4;
    const float4* s4 = reinterpret_cast<const float4*>(s);
    const float4* t4 = reinterpret_cast<const float4*>(t);

    float acc = 0.0f;
    int stride = nblk * NTHR;
    for (int i = blockIdx.x * NTHR + threadIdx.x; i < n_vec; i += stride) {
        float4 sv = s4[i];
        float4 tv = t4[i];
        acc += tv.x * __logf(sv.x);
        acc += tv.y * __logf(sv.y);
        acc += tv.z * __logf(sv.z);
        acc += tv.w * __logf(sv.w);
    }
    if (blockIdx.x == 0) {
        for (int i = tail0 + threadIdx.x; i < n; i += NTHR)
            acc += t[i] * __logf(s[i]);
    }

    finish(acc, inv_B, out, nblk);
}

extern "C" void kernel_launch(void* const* d_in, const int* in_sizes, int n_in,
                              void* d_out, int out_size)
{
    const float* s = (const float*)d_in[0];  // preds_s
    const float* t = (const float*)d_in[1];  // preds_t
    float* out = (float*)d_out;

    int n = in_sizes[0];
    float inv_B = (n == 4096000) ? (1.0f / 4096.0f) : (1000.0f / (float)n);

    int n_vec = n / 4;
    int per_block = NTHR * VPT;     // 1024 vectors per block

    if ((n % 4 == 0) && (n_vec % per_block == 0) && (n_vec / per_block) <= MAXBLK) {
        int nblk = n_vec / per_block;           // 1000 for this problem
        int stride = nblk * NTHR;               // 256,000
        fused_reduce_exact<<<nblk, NTHR>>>(
            reinterpret_cast<const float4*>(s),
            reinterpret_cast<const float4*>(t),
            stride, inv_B, out, nblk);
    } else {
        int nblk = 1024;
        fused_reduce_generic<<<nblk, NTHR>>>(s, t, n, inv_B, out, nblk);
    }
}